// round 1
// baseline (speedup 1.0000x reference)
#include <cuda_runtime.h>
#include <math.h>

// Problem constants
#define B_      256
#define L_      128
#define S_      128      // STATE
#define NG      5        // gates
#define NBLK    128      // persistent blocks (<= SM count, 1/SM via smem)
#define ROWS    16       // batch rows per block
#define COLS    16       // state cols per block
#define NTHR    256

// Cross-block state (no allocation allowed -> __device__ globals)
__device__ float    g_h[2][S_ * B_];   // [buf][k*B + b]
__device__ unsigned g_bar;
__device__ unsigned g_done;

// Shared memory layout (floats):
//  WL   [ (g*COLS+c)*S_ + k ]   : 5*16*128 = 10240
//  WR   same                    : 10240
//  SH   [ k*17 + row ]          : 128*17 = 2176  (pad 17 -> conflict free)
//  SX   [ k*17 + row ]          : 2176
//  SB   [ g*COLS + c ]          : 80
//  SID  16 ints
#define OFF_WL   0
#define OFF_WR   10240
#define OFF_SH   20480
#define OFF_SX   22656
#define OFF_SB   24832
#define OFF_SID  24912
#define SMEM_REQ 131072  // force 1 block / SM for barrier residency

__device__ __forceinline__ float sigm(float x) {
    return 1.0f / (1.0f + expf(-x));
}

extern "C" __global__ void __launch_bounds__(NTHR, 1)
tac_lstm_kernel(const int*   __restrict__ ids,
                const float* __restrict__ embed,
                const float* __restrict__ whx_w,
                const float* __restrict__ whx_b,
                const float* __restrict__ init_state,
                const float* __restrict__ final_w,
                const float* __restrict__ final_b,
                float*       __restrict__ out)
{
    extern __shared__ float sm[];
    float* WL  = sm + OFF_WL;
    float* WR  = sm + OFF_WR;
    float* SH  = sm + OFF_SH;
    float* SX  = sm + OFF_SX;
    float* SB  = sm + OFF_SB;
    int*   SID = (int*)(sm + OFF_SID);

    const int tid = threadIdx.x;
    const int row = tid & 15;        // batch row within block
    const int col = tid >> 4;        // state col within block
    const int bid = blockIdx.x;
    const int cg  = bid & 7;         // 8 col groups  * 16 cols = 128 state dims
    const int rg  = bid >> 3;        // 16 row groups * 16 rows = 256 batch rows
    const int colbase = cg * COLS;
    const int rowbase = rg * ROWS;
    const int colglob = colbase + col;
    const int rowglob = rowbase + row;

    // ---- one-time: load this block's weight slices into smem ----
    // idx -> (c, g, k) with k fastest => coalesced global reads
    for (int idx = tid; idx < COLS * NG * S_; idx += NTHR) {
        int k = idx & 127;
        int g = (idx >> 7) % NG;
        int c = idx / (NG * S_);
        int j = g * S_ + colbase + c;            // global gate-row (0..639)
        WL[(g * COLS + c) * S_ + k] = whx_w[j * 256 + k];
        WR[(g * COLS + c) * S_ + k] = whx_w[j * 256 + 128 + k];
    }
    if (tid < NG * COLS) {
        int g = tid / COLS, c = tid % COLS;
        SB[tid] = whx_b[g * S_ + colbase + c];
    }

    // ---- init h0 (each block writes its disjoint [k-slice, b-slice]) ----
    g_h[0][colglob * B_ + rowglob] = init_state[colglob];
    // per-thread persistent cell state
    float cstate = init_state[S_ + colglob];

    // grid barrier helper state
    unsigned target = NBLK;
    __threadfence();
    __syncthreads();
    if (tid == 0) {
        atomicAdd(&g_bar, 1u);
        while (*(volatile unsigned*)&g_bar < target) { }
    }
    __syncthreads();

    const float4* WL4 = (const float4*)WL;
    const float4* WR4 = (const float4*)WR;

    // ================= sequential scan =================
    for (int t = 0; t < L_; t++) {
        const float* hbuf  = g_h[t & 1];
        float*       hnext = g_h[(t + 1) & 1];

        // fetch token ids for this block's rows
        if (tid < ROWS) SID[tid] = ids[(rowbase + tid) * L_ + t];

        // load h tile into smem (L2 reads, bypass stale L1)
        #pragma unroll
        for (int i = 0; i < 8; i++) {
            int k = i * 16 + col;
            SH[k * 17 + row] = __ldcg(&hbuf[k * B_ + rowbase + row]);
        }
        __syncthreads();

        // gather x (right_h) into smem: 16 threads per row, coalesced per row
        {
            int r2 = tid >> 4, l2 = tid & 15;
            const float* eb = embed + (size_t)SID[r2] * 256;
            #pragma unroll
            for (int i = 0; i < 8; i++) {
                int k = i * 16 + l2;
                SX[k * 17 + r2] = __ldg(&eb[k]);
            }
        }
        __syncthreads();

        // ---- GEMM: z = left_h @ Wl^T + right_h @ Wr^T  (this block's 16x80 tile) ----
        float accL[NG] = {0.f, 0.f, 0.f, 0.f, 0.f};
        float accR[NG] = {0.f, 0.f, 0.f, 0.f, 0.f};
        #pragma unroll 4
        for (int kc = 0; kc < 32; kc++) {
            float h0 = SH[(4 * kc + 0) * 17 + row];
            float h1 = SH[(4 * kc + 1) * 17 + row];
            float h2 = SH[(4 * kc + 2) * 17 + row];
            float h3 = SH[(4 * kc + 3) * 17 + row];
            float x0 = SX[(4 * kc + 0) * 17 + row];
            float x1 = SX[(4 * kc + 1) * 17 + row];
            float x2 = SX[(4 * kc + 2) * 17 + row];
            float x3 = SX[(4 * kc + 3) * 17 + row];
            #pragma unroll
            for (int g = 0; g < NG; g++) {
                float4 wl = WL4[(g * COLS + col) * 32 + kc];
                accL[g] = fmaf(wl.x, h0, fmaf(wl.y, h1, fmaf(wl.z, h2, fmaf(wl.w, h3, accL[g]))));
                float4 wr = WR4[(g * COLS + col) * 32 + kc];
                accR[g] = fmaf(wr.x, x0, fmaf(wr.y, x1, fmaf(wr.z, x2, fmaf(wr.w, x3, accR[g]))));
            }
        }

        // ---- gate update ----
        float za  = accL[0] + accR[0] + SB[0 * COLS + col];
        float zi  = accL[1] + accR[1] + SB[1 * COLS + col];
        float zf1 = accL[2] + accR[2] + SB[2 * COLS + col];
        float zf2 = accL[3] + accR[3] + SB[3 * COLS + col];
        float zo  = accL[4] + accR[4] + SB[4 * COLS + col];

        float rc = __ldg(&embed[(size_t)SID[row] * 256 + 128 + colglob]);  // right_c

        cstate = tanhf(za) * sigm(zi) + sigm(zf1) * cstate + sigm(zf2) * rc;
        float hval = sigm(zo) * tanhf(cstate);

        hnext[colglob * B_ + rowglob] = hval;

        // ---- grid barrier ----
        __threadfence();
        __syncthreads();
        target += NBLK;
        if (tid == 0) {
            atomicAdd(&g_bar, 1u);
            while (*(volatile unsigned*)&g_bar < target) { }
        }
        __syncthreads();
    }

    // ================= final projection: out = h @ final_w^T + final_b =================
    // final h lives in g_h[0]. Blocks with cg==0 handle their 16 rows.
    if (cg == 0) {
        int r2 = tid >> 4;        // row within block
        int l2 = tid & 15;        // k-split lane (8 k's each)
        float p0 = 0.f, p1 = 0.f, p2 = 0.f;
        #pragma unroll
        for (int i = 0; i < 8; i++) {
            int k = l2 * 8 + i;
            float hv = __ldcg(&g_h[0][k * B_ + rowbase + r2]);
            p0 = fmaf(hv, __ldg(&final_w[0 * S_ + k]), p0);
            p1 = fmaf(hv, __ldg(&final_w[1 * S_ + k]), p1);
            p2 = fmaf(hv, __ldg(&final_w[2 * S_ + k]), p2);
        }
        // reduce across the 16 k-split lanes (lanes 0-15 / 16-31 are separate rows)
        #pragma unroll
        for (int off = 8; off > 0; off >>= 1) {
            p0 += __shfl_down_sync(0xffffffffu, p0, off, 16);
            p1 += __shfl_down_sync(0xffffffffu, p1, off, 16);
            p2 += __shfl_down_sync(0xffffffffu, p2, off, 16);
        }
        if (l2 == 0) {
            int b = rowbase + r2;
            out[b * 3 + 0] = p0 + __ldg(&final_b[0]);
            out[b * 3 + 1] = p1 + __ldg(&final_b[1]);
            out[b * 3 + 2] = p2 + __ldg(&final_b[2]);
        }
    }

    // ---- reset barrier counters for the next graph replay (deterministic) ----
    __threadfence();
    __syncthreads();
    if (tid == 0) {
        unsigned v = atomicAdd(&g_done, 1u);
        if (v == NBLK - 1) {          // last arriver: everyone has passed all spins
            g_bar  = 0u;
            g_done = 0u;
            __threadfence();
        }
    }
}

extern "C" void kernel_launch(void* const* d_in, const int* in_sizes, int n_in,
                              void* d_out, int out_size)
{
    // Identify inputs robustly by element count (all distinct).
    const int*   ids        = nullptr;
    const float* embed      = nullptr;
    const float* whx_w      = nullptr;
    const float* whx_b      = nullptr;
    const float* init_state = nullptr;
    const float* final_w    = nullptr;
    const float* final_b    = nullptr;
    for (int i = 0; i < n_in; i++) {
        switch (in_sizes[i]) {
            case 256 * 128:      ids        = (const int*)d_in[i];   break; // (B,L) int32
            case 50000 * 256:    embed      = (const float*)d_in[i]; break;
            case 640 * 256:      whx_w      = (const float*)d_in[i]; break;
            case 640:            whx_b      = (const float*)d_in[i]; break;
            case 256:            init_state = (const float*)d_in[i]; break;
            case 3 * 128:        final_w    = (const float*)d_in[i]; break;
            case 3:              final_b    = (const float*)d_in[i]; break;
            default: break;
        }
    }
    float* out = (float*)d_out;

    cudaFuncSetAttribute(tac_lstm_kernel,
                         cudaFuncAttributeMaxDynamicSharedMemorySize, SMEM_REQ);
    tac_lstm_kernel<<<NBLK, NTHR, SMEM_REQ>>>(ids, embed, whx_w, whx_b,
                                              init_state, final_w, final_b, out);
}